// round 14
// baseline (speedup 1.0000x reference)
#include <cuda_runtime.h>
#include <cstdint>

// RRSVM rank-weighted pooling, 3x3 window, stride 2, pad 1.
// x: [32, 64, 112, 112] f32   s: [64, 3, 3] f32
// d_out (f32, concatenated): out [32,64,56,56], order [32,64,56,56,9]
// 2 pixels/thread, per-WARP TMA order writes (no block-wide epilogue sync),
// read-only drain, regs capped at 32 for 8 CTAs/SM.

#define BB 32
#define CC 64
#define HH 112
#define WW 112
#define HO 56
#define WO 56
#define PIX_PER_CH (HO * WO)           // 3136
#define PAIRS_PER_CH (PIX_PER_CH / 2)  // 1568
#define UPR (WO / 2)                   // 28 thread-pairs per output row
#define NQ (BB * CC)                   // 2048
#define TPB 256
#define WARP_BYTES (32 * 18 * 4)       // 2304 per warp slice

// Ranks (x4, byte offsets) of 9 values; strict-greater => stable.
__device__ __forceinline__ void ranks9(const float v[9], int ir[9]) {
    float rf[9];
    #pragma unroll
    for (int k = 0; k < 9; k++) rf[k] = (float)(4 * k);
    #pragma unroll
    for (int i = 0; i < 8; i++) {
        #pragma unroll
        for (int j = i + 1; j < 9; j++) {
            float m;
            asm("set.gt.f32.f32 %0, %1, %2;"
                : "=f"(m) : "f"(v[j]), "f"(v[i]));
            rf[i] = fmaf(m,  4.0f, rf[i]);
            rf[j] = fmaf(m, -4.0f, rf[j]);
        }
    }
    #pragma unroll
    for (int k = 0; k < 9; k++) ir[k] = (int)rf[k];
}

__device__ __forceinline__ void stcs_f2(float* p, float2 v) {
    asm volatile("st.global.cs.v2.f32 [%0], {%1,%2};"
                 :: "l"(p), "f"(v.x), "f"(v.y) : "memory");
}

__global__ void __launch_bounds__(TPB, 8) rrsvm_kernel(
        const float* __restrict__ x,
        const float* __restrict__ s,
        float* __restrict__ out,
        float* __restrict__ order,
        int write_order) {
    __shared__ __align__(16) float ord_sh[TPB * 18];  // 18,432 B staging
    __shared__ float s_sh[18];

    const int tid = threadIdx.x;
    const unsigned t0 = blockIdx.x * TPB;      // first pair index of block
    const unsigned t = t0 + tid;               // this thread's pair index

    const int q_first = (int)(t0 / PAIRS_PER_CH);
    const int q = (int)(t / PAIRS_PER_CH);

    if (tid < 18) {
        int qq = q_first + tid / 9;
        if (qq < NQ) s_sh[tid] = s[(qq & (CC - 1)) * 9 + (tid % 9)];
    }
    __syncthreads();

    const int cbase = (q - q_first) * 9;       // 0 or 9
    const int pr = (int)(t % PAIRS_PER_CH);
    const int ho = pr / UPR;
    const int u  = pr % UPR;                   // pixel A: wo=2u, pixel B: wo=2u+1
    const int lane = tid & 31;

    const float* xp = x + (unsigned)q * (HH * WW);
    const float* row0 = xp + (2 * ho - 1) * WW + 4 * u;
    const bool h0v = (ho > 0);

    // One float4 per window row covers cols 4u..4u+3 (16B-aligned).
    float4 r0 = make_float4(0.f, 0.f, 0.f, 0.f), r1, r2;
    if (h0v) r0 = *(const float4*)(row0);
    r1 = *(const float4*)(row0 + WW);
    r2 = *(const float4*)(row0 + 2 * WW);

    // Left col 4u-1 = lane-1's .w (consecutive t => u-1 same row when u>0).
    float l0 = __shfl_up_sync(0xffffffffu, r0.w, 1);
    float l1 = __shfl_up_sync(0xffffffffu, r1.w, 1);
    float l2 = __shfl_up_sync(0xffffffffu, r2.w, 1);
    if (lane == 0 && u > 0) {
        if (h0v) l0 = __ldg(row0 - 1);
        l1 = __ldg(row0 + WW - 1);
        l2 = __ldg(row0 + 2 * WW - 1);
    }
    if (u == 0) { l0 = 0.f; l1 = 0.f; l2 = 0.f; }   // wo==0 -> pad
    if (!h0v) l0 = 0.f;

    const char* sp = (const char*)(s_sh + cbase);
    float2 res;

    // ---- pixel A: window cols 4u-1, 4u, 4u+1 ----
    {
        float v[9] = { l0, r0.x, r0.y,  l1, r1.x, r1.y,  l2, r2.x, r2.y };
        int ir[9];
        ranks9(v, ir);
        float sum = 0.f;
        #pragma unroll
        for (int k = 0; k < 9; k++) sum += v[k] * *(const float*)(sp + ir[k]);
        res.x = sum;
        if (write_order) {
            char* my = (char*)(ord_sh + tid * 18);
            #pragma unroll
            for (int k = 0; k < 9; k++) *(float*)(my + ir[k]) = (float)k;
        }
    }
    // ---- pixel B: window cols 4u+1, 4u+2, 4u+3 ----
    {
        float v[9] = { r0.y, r0.z, r0.w,  r1.y, r1.z, r1.w,  r2.y, r2.z, r2.w };
        int ir[9];
        ranks9(v, ir);
        float sum = 0.f;
        #pragma unroll
        for (int k = 0; k < 9; k++) sum += v[k] * *(const float*)(sp + ir[k]);
        res.y = sum;
        if (write_order) {
            char* my = (char*)(ord_sh + tid * 18 + 9);
            #pragma unroll
            for (int k = 0; k < 9; k++) *(float*)(my + ir[k]) = (float)k;
        }
    }

    stcs_f2(out + 2ull * t, res);

    if (write_order) {
        // Per-warp epilogue: no block-wide sync; each warp ships its own
        // contiguous 2304-byte slice via the bulk-async engine.
        __syncwarp();
        if (lane == 0) {
            const int w = tid >> 5;
            const float* sbuf = ord_sh + w * (32 * 18);
            float* gdst = order + ((unsigned long long)(t0 + w * 32)) * 18ull;
            asm volatile("fence.proxy.async.shared::cta;" ::: "memory");
            uint32_t saddr;
            asm("{ .reg .u64 a; cvta.to.shared.u64 a, %1; cvt.u32.u64 %0, a; }"
                : "=r"(saddr) : "l"(sbuf));
            asm volatile(
                "cp.async.bulk.global.shared::cta.bulk_group [%0], [%1], %2;"
                :: "l"(gdst), "r"(saddr), "r"((unsigned)WARP_BYTES)
                : "memory");
            asm volatile("cp.async.bulk.commit_group;" ::: "memory");
            // Wait only for the smem READ; global writes drain past exit.
            asm volatile("cp.async.bulk.wait_group.read 0;" ::: "memory");
        }
    }
}

extern "C" void kernel_launch(void* const* d_in, const int* in_sizes, int n_in,
                              void* d_out, int out_size) {
    const float* x = (const float*)d_in[0];
    const float* s = (const float*)d_in[1];
    const long long NPIX = (long long)BB * CC * HO * WO;  // 6,422,528

    float* out = (float*)d_out;
    float* order = out + NPIX;
    int write_order = ((long long)out_size >= NPIX * 10LL) ? 1 : 0;

    const long long pairs = NPIX / 2;                    // 3,211,264
    const long long blocks = pairs / TPB;                // 12544, exact
    rrsvm_kernel<<<(unsigned)blocks, TPB>>>(x, s, out, order, write_order);
}

// round 15
// speedup vs baseline: 1.0422x; 1.0422x over previous
#include <cuda_runtime.h>
#include <cstdint>

// RRSVM rank-weighted pooling, 3x3 window, stride 2, pad 1.
// x: [32, 64, 112, 112] f32   s: [64, 3, 3] f32
// d_out (f32, concatenated): out [32,64,56,56], order [32,64,56,56,9]
// 2 pixels/thread, s gathered via warp shuffle (no smem s table),
// block TMA order write with read-only drain, regs capped for 8 CTAs/SM.

#define BB 32
#define CC 64
#define HH 112
#define WW 112
#define HO 56
#define WO 56
#define PIX_PER_CH (HO * WO)           // 3136
#define PAIRS_PER_CH (PIX_PER_CH / 2)  // 1568 (multiple of 32: warp = 1 channel)
#define UPR (WO / 2)                   // 28 thread-pairs per output row
#define TPB 256
#define TILE_BYTES (TPB * 18 * 4)      // 18432

// Ranks (0..8) of 9 values; strict-greater => stable (ties keep index order).
__device__ __forceinline__ void ranks9(const float v[9], int ir[9]) {
    float rf[9];
    #pragma unroll
    for (int k = 0; k < 9; k++) rf[k] = (float)k;
    #pragma unroll
    for (int i = 0; i < 8; i++) {
        #pragma unroll
        for (int j = i + 1; j < 9; j++) {
            float m;
            asm("set.gt.f32.f32 %0, %1, %2;"
                : "=f"(m) : "f"(v[j]), "f"(v[i]));
            rf[i] = fmaf(m,  1.0f, rf[i]);
            rf[j] = fmaf(m, -1.0f, rf[j]);
        }
    }
    #pragma unroll
    for (int k = 0; k < 9; k++) ir[k] = (int)rf[k];
}

__device__ __forceinline__ void stcs_f2(float* p, float2 v) {
    asm volatile("st.global.cs.v2.f32 [%0], {%1,%2};"
                 :: "l"(p), "f"(v.x), "f"(v.y) : "memory");
}

__global__ void __launch_bounds__(TPB, 8) rrsvm_kernel(
        const float* __restrict__ x,
        const float* __restrict__ s,
        float* __restrict__ out,
        float* __restrict__ order,
        int write_order) {
    __shared__ __align__(16) float ord_sh[TPB * 18];  // 18,432 B staging

    const int tid = threadIdx.x;
    const unsigned t0 = blockIdx.x * TPB;      // first pair index of block
    const unsigned t = t0 + tid;               // this thread's pair index

    const int q = (int)(t / PAIRS_PER_CH);
    const int pr = (int)(t % PAIRS_PER_CH);
    const int ho = pr / UPR;
    const int u  = pr % UPR;                   // pixel A: wo=2u, pixel B: wo=2u+1
    const int lane = tid & 31;

    // Whole warp shares one channel (1568 % 32 == 0). Lanes 0-8 hold the
    // channel's s row; gather by rank via shfl.idx.
    const int c = q & (CC - 1);
    float sval = 0.0f;
    if (lane < 9) sval = __ldg(s + c * 9 + lane);

    const float* xp = x + (unsigned)q * (HH * WW);
    const float* row0 = xp + (2 * ho - 1) * WW + 4 * u;
    const bool h0v = (ho > 0);

    // One float4 per window row covers cols 4u..4u+3 (16B-aligned).
    float4 r0 = make_float4(0.f, 0.f, 0.f, 0.f), r1, r2;
    if (h0v) r0 = *(const float4*)(row0);
    r1 = *(const float4*)(row0 + WW);
    r2 = *(const float4*)(row0 + 2 * WW);

    // Left col 4u-1 = lane-1's .w (consecutive t => u-1 same row when u>0).
    float l0 = __shfl_up_sync(0xffffffffu, r0.w, 1);
    float l1 = __shfl_up_sync(0xffffffffu, r1.w, 1);
    float l2 = __shfl_up_sync(0xffffffffu, r2.w, 1);
    if (lane == 0 && u > 0) {
        if (h0v) l0 = __ldg(row0 - 1);
        l1 = __ldg(row0 + WW - 1);
        l2 = __ldg(row0 + 2 * WW - 1);
    }
    if (u == 0) { l0 = 0.f; l1 = 0.f; l2 = 0.f; }   // wo==0 -> pad
    if (!h0v) l0 = 0.f;

    float2 res;

    // ---- pixel A: window cols 4u-1, 4u, 4u+1 ----
    {
        float v[9] = { l0, r0.x, r0.y,  l1, r1.x, r1.y,  l2, r2.x, r2.y };
        int ir[9];
        ranks9(v, ir);
        float sum = 0.f;
        #pragma unroll
        for (int k = 0; k < 9; k++)
            sum += v[k] * __shfl_sync(0xffffffffu, sval, ir[k]);
        res.x = sum;
        if (write_order) {
            float* my = ord_sh + tid * 18;
            #pragma unroll
            for (int k = 0; k < 9; k++) my[ir[k]] = (float)k;
        }
    }
    // ---- pixel B: window cols 4u+1, 4u+2, 4u+3 ----
    {
        float v[9] = { r0.y, r0.z, r0.w,  r1.y, r1.z, r1.w,  r2.y, r2.z, r2.w };
        int ir[9];
        ranks9(v, ir);
        float sum = 0.f;
        #pragma unroll
        for (int k = 0; k < 9; k++)
            sum += v[k] * __shfl_sync(0xffffffffu, sval, ir[k]);
        res.y = sum;
        if (write_order) {
            float* my = ord_sh + tid * 18 + 9;
            #pragma unroll
            for (int k = 0; k < 9; k++) my[ir[k]] = (float)k;
        }
    }

    stcs_f2(out + 2ull * t, res);

    if (write_order) {
        __syncthreads();
        if (tid == 0) {
            asm volatile("fence.proxy.async.shared::cta;" ::: "memory");
            uint32_t saddr;
            asm("{ .reg .u64 a; cvta.to.shared.u64 a, %1; cvt.u32.u64 %0, a; }"
                : "=r"(saddr) : "l"(ord_sh));
            float* gdst = order + (unsigned long long)t0 * 18ull;
            asm volatile(
                "cp.async.bulk.global.shared::cta.bulk_group [%0], [%1], %2;"
                :: "l"(gdst), "r"(saddr), "r"((unsigned)TILE_BYTES)
                : "memory");
            asm volatile("cp.async.bulk.commit_group;" ::: "memory");
            // Wait only for the smem READ; global writes drain past exit.
            asm volatile("cp.async.bulk.wait_group.read 0;" ::: "memory");
        }
    }
}

extern "C" void kernel_launch(void* const* d_in, const int* in_sizes, int n_in,
                              void* d_out, int out_size) {
    const float* x = (const float*)d_in[0];
    const float* s = (const float*)d_in[1];
    const long long NPIX = (long long)BB * CC * HO * WO;  // 6,422,528

    float* out = (float*)d_out;
    float* order = out + NPIX;
    int write_order = ((long long)out_size >= NPIX * 10LL) ? 1 : 0;

    const long long pairs = NPIX / 2;                    // 3,211,264
    const long long blocks = pairs / TPB;                // 12544, exact
    rrsvm_kernel<<<(unsigned)blocks, TPB>>>(x, s, out, order, write_order);
}